// round 8
// baseline (speedup 1.0000x reference)
#include <cuda_runtime.h>
#include <cuda_fp16.h>
#include <cstdint>

// Problem constants (fixed by dataset)
#define NB    16
#define INCC  32
#define INNX  65536
#define OUTCC 32
#define OUTNX 8192
#define MAXD  16
#define NF    512     // NB*INCC feature columns
#define OB    8       // output nodes per CTA (one per warp)

// 64 MB fp16 feature table: feat[inn][j] = x[n,c,inn]*weight[c,inn], j = n*32+c
__device__ __half g_feat_h[(size_t)INNX * NF];

// ---- dynamic smem layout for gather kernel ----
#define SM_BUF    0                    // 8 warps * 16 KB row buffers
#define SM_POOL   131072               // 8 * 512 floats
#define SM_STAGE  147456               // 512 * 9 floats
#define SM_MBAR   165888               // 8 warps * 2 mbarriers * 8 B
#define SM_IS64   166016
#define SM_TOTAL  166080

// ---- packed f32x2 helpers (sm_103a FFMA2) ----
__device__ __forceinline__ unsigned long long pk2(float lo, float hi) {
    unsigned long long r;
    asm("mov.b64 %0,{%1,%2};" : "=l"(r) : "f"(lo), "f"(hi));
    return r;
}
__device__ __forceinline__ void upk2(unsigned long long v, float& lo, float& hi) {
    asm("mov.b64 {%0,%1},%2;" : "=f"(lo), "=f"(hi) : "l"(v));
}
__device__ __forceinline__ unsigned long long ffma2(unsigned long long a,
                                                    unsigned long long b,
                                                    unsigned long long c) {
    unsigned long long d;
    asm("fma.rn.f32x2 %0,%1,%2,%3;" : "=l"(d) : "l"(a), "l"(b), "l"(c));
    return d;
}

__device__ __forceinline__ uint32_t smem_u32(const void* p) {
    uint32_t a;
    asm("{ .reg .u64 t; cvta.to.shared.u64 t, %1; cvt.u32.u64 %0, t; }"
        : "=r"(a) : "l"(p));
    return a;
}

#define MBAR_INIT(mbar, cnt) \
    asm volatile("mbarrier.init.shared.b64 [%0], %1;" :: "r"(mbar), "r"(cnt) : "memory")
#define MBAR_EXPECT_TX(mbar, bytes) \
    asm volatile("mbarrier.arrive.expect_tx.shared.b64 _, [%0], %1;" \
                 :: "r"(mbar), "r"(bytes) : "memory")
#define TMA_BULK_G2S(dst, src, bytes, mbar) \
    asm volatile("cp.async.bulk.shared::cluster.global.mbarrier::complete_tx::bytes " \
                 "[%0], [%1], %2, [%3];" \
                 :: "r"(dst), "l"(src), "r"(bytes), "r"(mbar) : "memory")

__device__ __forceinline__ void mbar_wait(uint32_t mbar, uint32_t parity) {
    uint32_t done;
    asm volatile(
        "{\n\t.reg .pred p;\n\t"
        "mbarrier.try_wait.parity.shared.b64 p, [%1], %2;\n\t"
        "selp.b32 %0, 1, 0, p;\n\t}"
        : "=r"(done) : "r"(mbar), "r"(parity) : "memory");
    while (!done) {
        asm volatile(
            "{\n\t.reg .pred p;\n\t"
            "mbarrier.try_wait.parity.shared.b64 p, [%1], %2, 0x989680;\n\t"
            "selp.b32 %0, 1, 0, p;\n\t}"
            : "=r"(done) : "r"(mbar), "r"(parity) : "memory");
    }
}

// ---------------------------------------------------------------------------
// Kernel 1 (unchanged, proven ~33us): fused scale + transpose + fp32->fp16.
// ---------------------------------------------------------------------------
__global__ __launch_bounds__(256) void prep_kernel(const float* __restrict__ x,
                                                   const float* __restrict__ w) {
    __shared__ __half2 t2[32][65];
    const unsigned inn0 = blockIdx.x << 6;
    const unsigned j0   = blockIdx.y << 6;
    const unsigned tx = threadIdx.x, ty = threadIdx.y;   // 32 x 8

#pragma unroll
    for (int k = 0; k < 4; k++) {
        const unsigned jh = ty + (k << 3);
        const unsigned j  = j0 + 2 * jh;
        const unsigned c0 = j & 31;
        const unsigned c1 = (j + 1) & 31;
        const unsigned bx0 = j * INNX + inn0 + tx;
        const unsigned bw0 = c0 * INNX + inn0 + tx;
        const unsigned bw1 = c1 * INNX + inn0 + tx;
        const float a0 = __ldcs(x + bx0)              * __ldg(w + bw0);
        const float b0 = __ldcs(x + bx0 + INNX)       * __ldg(w + bw1);
        const float a1 = __ldcs(x + bx0 + 32)         * __ldg(w + bw0 + 32);
        const float b1 = __ldcs(x + bx0 + INNX + 32)  * __ldg(w + bw1 + 32);
        t2[jh][tx]      = __floats2half2_rn(a0, b0);
        t2[jh][tx + 32] = __floats2half2_rn(a1, b1);
    }
    __syncthreads();

    __half2* out2 = (__half2*)g_feat_h;   // row stride = 256 half2
    const unsigned tid = (ty << 5) + tx;
#pragma unroll
    for (int k = 0; k < 8; k++) {
        const unsigned e     = tid + (k << 8);
        const unsigned inn_l = e >> 5;
        const unsigned jh    = e & 31;
        out2[(inn0 + inn_l) * 256u + (j0 >> 1) + jh] = t2[jh][inn_l];
    }
}

// ---------------------------------------------------------------------------
// Kernel 2: warp-per-output-node with TMA-bulk row gather into smem.
// Lane 0 issues 16 x 1KB cp.async.bulk copies (two 8KB batches, two
// mbarriers); pooling reads rows from smem (conflict-free LDS.128, HFMA2);
// then permuted pooled smem + FFMA2 GEMM + staged transposed store (R7 path).
// ---------------------------------------------------------------------------
__global__ __launch_bounds__(256) void gather_kernel(
    const void*  __restrict__ Araw,
    const float* __restrict__ mask,
    const float* __restrict__ mw,
    const float* __restrict__ ctw,
    const float* __restrict__ ctb,
    const float* __restrict__ bias,
    float* __restrict__ out)
{
    extern __shared__ __align__(16) char smem[];
    const int tid  = threadIdx.x;
    const int w    = tid >> 5;
    const int lane = tid & 31;

    const uint32_t sbase = smem_u32(smem);
    const uint32_t buf   = sbase + SM_BUF + w * 16384;
    const uint32_t mbarA = sbase + SM_MBAR + w * 16;
    const uint32_t mbarB = mbarA + 8;
    float* s_pool  = (float*)(smem + SM_POOL + w * 2048);
    float* s_stage = (float*)(smem + SM_STAGE);
    int*   s_is64  = (int*)(smem + SM_IS64);

    if (tid == 0) {
        const long long* a64 = (const long long*)Araw;
        int is64 = 1;
#pragma unroll
        for (int i = 0; i < 8; i++)
            if ((unsigned long long)a64[i] >= (unsigned long long)INNX) is64 = 0;
        *s_is64 = is64;
    }
    __syncthreads();
    const int is64 = *s_is64;

    const int o_base = blockIdx.x * OB;
    const int o      = o_base + w;

    // neighbor indices + pooling weights, distributed in lanes 0..15
    unsigned av = 0;
    float    wv = 0.f;
    if (lane < MAXD) {
        av = is64 ? (unsigned)((const long long*)Araw)[(size_t)o * MAXD + lane]
                  : (unsigned)((const int*)Araw)[(size_t)o * MAXD + lane];
        wv = mw[o * MAXD + lane] * mask[o * MAXD + lane];
    }

    // ---- issue TMA bulk gathers (lane 0), two 8KB batches ----
    if (lane == 0) {
        MBAR_INIT(mbarA, 1);
        MBAR_INIT(mbarB, 1);
    }
    __syncwarp();
    if (lane == 0) MBAR_EXPECT_TX(mbarA, 8192);
    __syncwarp();
    const char* fbase = (const char*)g_feat_h;
#pragma unroll
    for (int d = 0; d < 8; d++) {
        const unsigned idx = __shfl_sync(0xffffffffu, av, d);
        if (lane == 0)
            TMA_BULK_G2S(buf + d * 1024, fbase + (size_t)idx * 1024, 1024, mbarA);
    }
    if (lane == 0) MBAR_EXPECT_TX(mbarB, 8192);
    __syncwarp();
#pragma unroll
    for (int d = 8; d < 16; d++) {
        const unsigned idx = __shfl_sync(0xffffffffu, av, d);
        if (lane == 0)
            TMA_BULK_G2S(buf + d * 1024, fbase + (size_t)idx * 1024, 1024, mbarB);
    }

    // ---- pool from smem in half2 (HFMA2), batch A then batch B ----
    __half2 acc[8];
#pragma unroll
    for (int i = 0; i < 8; i++) acc[i] = __float2half2_rn(0.f);

    const char* bufc = smem + SM_BUF + w * 16384;
    mbar_wait(mbarA, 0);
#pragma unroll
    for (int d = 0; d < 8; d++) {
        const float   wd = __shfl_sync(0xffffffffu, wv, d);
        const __half2 wh = __half2half2(__float2half_rn(wd));
        uint4 u0 = *(const uint4*)(bufc + d * 1024 + lane * 16);
        uint4 u1 = *(const uint4*)(bufc + d * 1024 + 512 + lane * 16);
        const __half2* h0 = (const __half2*)&u0;
        const __half2* h1 = (const __half2*)&u1;
#pragma unroll
        for (int q = 0; q < 4; q++) {
            acc[q]     = __hfma2(h0[q], wh, acc[q]);
            acc[4 + q] = __hfma2(h1[q], wh, acc[4 + q]);
        }
    }
    mbar_wait(mbarB, 0);
#pragma unroll
    for (int d = 8; d < 16; d++) {
        const float   wd = __shfl_sync(0xffffffffu, wv, d);
        const __half2 wh = __half2half2(__float2half_rn(wd));
        uint4 u0 = *(const uint4*)(bufc + d * 1024 + lane * 16);
        uint4 u1 = *(const uint4*)(bufc + d * 1024 + 512 + lane * 16);
        const __half2* h0 = (const __half2*)&u0;
        const __half2* h1 = (const __half2*)&u1;
#pragma unroll
        for (int q = 0; q < 4; q++) {
            acc[q]     = __hfma2(h0[q], wh, acc[q]);
            acc[4 + q] = __hfma2(h1[q], wh, acc[4 + q]);
        }
    }

    // permuted pooled stores: 4 coalesced conflict-free STS.128
    float4* sp4 = (float4*)s_pool;
    {
        float2 f0 = __half22float2(acc[0]), f1 = __half22float2(acc[1]);
        float2 f2 = __half22float2(acc[2]), f3 = __half22float2(acc[3]);
        float2 f4 = __half22float2(acc[4]), f5 = __half22float2(acc[5]);
        float2 f6 = __half22float2(acc[6]), f7 = __half22float2(acc[7]);
        sp4[lane]      = make_float4(f0.x, f0.y, f1.x, f1.y);
        sp4[32 + lane] = make_float4(f2.x, f2.y, f3.x, f3.y);
        sp4[64 + lane] = make_float4(f4.x, f4.y, f5.x, f5.y);
        sp4[96 + lane] = make_float4(f6.x, f6.y, f7.x, f7.y);
    }
    __syncwarp();

    // ---- ct_weight row packed in f32x2 regs ----
    unsigned long long wp[16];
    {
        const float4* cw4 = (const float4*)(ctw + lane * INCC);
#pragma unroll
        for (int q = 0; q < 8; q++) {
            float4 v = __ldg(cw4 + q);
            wp[2 * q]     = pk2(v.x, v.y);
            wp[2 * q + 1] = pk2(v.z, v.w);
        }
    }
    const float cb = __ldg(ctb + lane);

    // ---- GEMM in FFMA2 ----
    const ulonglong2* spv = (const ulonglong2*)s_pool;
#pragma unroll
    for (int t = 0; t < NB; t++) {
        unsigned long long y2 = pk2(cb, 0.f);
#pragma unroll
        for (int c4 = 0; c4 < 8; c4++) {
            const int idx = ((t >> 3) ? 64 : 0) + ((c4 & 1) ? 32 : 0)
                          + 4 * (t & 7) + (c4 >> 1);
            ulonglong2 pv = spv[idx];
            y2 = ffma2(pv.x, wp[2 * c4], y2);
            y2 = ffma2(pv.y, wp[2 * c4 + 1], y2);
        }
        float lo, hi; upk2(y2, lo, hi);
        s_stage[(t * 32 + lane) * (OB + 1) + w] = lo + hi;
    }
    __syncthreads();

    // ---- coalesced write-out: out[row*8192 + o] = stage + bias ----
#pragma unroll
    for (int e = tid; e < NF * OB; e += 256) {
        const int row  = e >> 3;
        const int col  = e & 7;
        const int oo   = o_base + col;
        const int dout = row & 31;
        out[(size_t)row * OUTNX + oo] =
            s_stage[row * (OB + 1) + col] + __ldg(bias + (size_t)dout * OUTNX + oo);
    }
}

extern "C" void kernel_launch(void* const* d_in, const int* in_sizes, int n_in,
                              void* d_out, int out_size) {
    const float* x    = (const float*)d_in[0];
    const void*  A    = d_in[1];
    const float* w    = (const float*)d_in[2];
    const float* mask = (const float*)d_in[3];
    const float* mw   = (const float*)d_in[4];
    const float* ctw  = (const float*)d_in[5];
    const float* ctb  = (const float*)d_in[6];
    const float* bias = (const float*)d_in[7];
    float* out = (float*)d_out;
    (void)in_sizes; (void)n_in; (void)out_size;

    cudaFuncSetAttribute(gather_kernel,
                         cudaFuncAttributeMaxDynamicSharedMemorySize, SM_TOTAL);

    dim3 pgrid(INNX / 64, NF / 64);
    dim3 pblk(32, 8);
    prep_kernel<<<pgrid, pblk>>>(x, w);

    gather_kernel<<<OUTNX / OB, 256, SM_TOTAL>>>(A, mask, mw, ctw, ctb, bias, out);
}

// round 9
// speedup vs baseline: 1.0484x; 1.0484x over previous
#include <cuda_runtime.h>
#include <cuda_fp16.h>
#include <cstdint>

// Problem constants (fixed by dataset)
#define NB    16
#define INCC  32
#define INNX  65536
#define OUTCC 32
#define OUTNX 8192
#define MAXD  16
#define NF    512     // NB*INCC feature columns
#define OB    8       // output nodes per CTA (one per warp)

// 64 MB fp16 feature table: feat[inn][j] = x[n,c,inn]*weight[c,inn], j = n*32+c
__device__ __half g_feat_h[(size_t)INNX * NF];

// ---- dynamic smem layout for gather kernel (per CTA) ----
#define SM_BUF    0        // 8 warps * 8 KB ring buffers = 65536
#define SM_POOL   65536    // 8 * 512 floats = 16384
#define SM_STAGE  81920    // 512 * 9 floats = 18432
#define SM_IS64   100352   // 4
#define SM_TOTAL  100416

// ---- packed f32x2 helpers (sm_103a FFMA2) ----
__device__ __forceinline__ unsigned long long pk2(float lo, float hi) {
    unsigned long long r;
    asm("mov.b64 %0,{%1,%2};" : "=l"(r) : "f"(lo), "f"(hi));
    return r;
}
__device__ __forceinline__ void upk2(unsigned long long v, float& lo, float& hi) {
    asm("mov.b64 {%0,%1},%2;" : "=f"(lo), "=f"(hi) : "l"(v));
}
__device__ __forceinline__ unsigned long long ffma2(unsigned long long a,
                                                    unsigned long long b,
                                                    unsigned long long c) {
    unsigned long long d;
    asm("fma.rn.f32x2 %0,%1,%2,%3;" : "=l"(d) : "l"(a), "l"(b), "l"(c));
    return d;
}

__device__ __forceinline__ uint32_t smem_u32(const void* p) {
    uint32_t a;
    asm("{ .reg .u64 t; cvta.to.shared.u64 t, %1; cvt.u32.u64 %0, t; }"
        : "=r"(a) : "l"(p));
    return a;
}

__device__ __forceinline__ void cpasync16(uint32_t dst, const void* src) {
    asm volatile("cp.async.cg.shared.global [%0], [%1], 16;"
                 :: "r"(dst), "l"(src) : "memory");
}

// ---------------------------------------------------------------------------
// Kernel 1 (unchanged, proven ~33us): fused scale + transpose + fp32->fp16.
// ---------------------------------------------------------------------------
__global__ __launch_bounds__(256) void prep_kernel(const float* __restrict__ x,
                                                   const float* __restrict__ w) {
    __shared__ __half2 t2[32][65];
    const unsigned inn0 = blockIdx.x << 6;
    const unsigned j0   = blockIdx.y << 6;
    const unsigned tx = threadIdx.x, ty = threadIdx.y;   // 32 x 8

#pragma unroll
    for (int k = 0; k < 4; k++) {
        const unsigned jh = ty + (k << 3);
        const unsigned j  = j0 + 2 * jh;
        const unsigned c0 = j & 31;
        const unsigned c1 = (j + 1) & 31;
        const unsigned bx0 = j * INNX + inn0 + tx;
        const unsigned bw0 = c0 * INNX + inn0 + tx;
        const unsigned bw1 = c1 * INNX + inn0 + tx;
        const float a0 = __ldcs(x + bx0)              * __ldg(w + bw0);
        const float b0 = __ldcs(x + bx0 + INNX)       * __ldg(w + bw1);
        const float a1 = __ldcs(x + bx0 + 32)         * __ldg(w + bw0 + 32);
        const float b1 = __ldcs(x + bx0 + INNX + 32)  * __ldg(w + bw1 + 32);
        t2[jh][tx]      = __floats2half2_rn(a0, b0);
        t2[jh][tx + 32] = __floats2half2_rn(a1, b1);
    }
    __syncthreads();

    __half2* out2 = (__half2*)g_feat_h;   // row stride = 256 half2
    const unsigned tid = (ty << 5) + tx;
#pragma unroll
    for (int k = 0; k < 8; k++) {
        const unsigned e     = tid + (k << 8);
        const unsigned inn_l = e >> 5;
        const unsigned jh    = e & 31;
        out2[(inn0 + inn_l) * 256u + (j0 >> 1) + jh] = t2[jh][inn_l];
    }
}

// ---------------------------------------------------------------------------
// Kernel 2: warp-per-output-node gather via per-lane cp.async.cg (LDGSTS).
// Each lane copies exactly the two 16B chunks it will pool (self-copy ->
// wait_group alone gives visibility, zero barriers). 4-row batches in an
// 8KB/warp double-buffered ring: issue b0,b1; wait(1); pool b0; issue b2; ...
// Pool = HFMA2 from smem; then permuted pooled smem + FFMA2 GEMM + staged
// transposed store (proven R7 path).
// ---------------------------------------------------------------------------
__global__ __launch_bounds__(256) void gather_kernel(
    const void*  __restrict__ Araw,
    const float* __restrict__ mask,
    const float* __restrict__ mw,
    const float* __restrict__ ctw,
    const float* __restrict__ ctb,
    const float* __restrict__ bias,
    float* __restrict__ out)
{
    extern __shared__ __align__(16) char smem[];
    const int tid  = threadIdx.x;
    const int w    = tid >> 5;
    const int lane = tid & 31;

    const uint32_t bufs = smem_u32(smem) + SM_BUF + w * 8192;
    const char*    bufc = smem + SM_BUF + w * 8192;
    float* s_pool  = (float*)(smem + SM_POOL + w * 2048);
    float* s_stage = (float*)(smem + SM_STAGE);
    int*   s_is64  = (int*)(smem + SM_IS64);

    if (tid == 0) {
        const long long* a64 = (const long long*)Araw;
        int is64 = 1;
#pragma unroll
        for (int i = 0; i < 8; i++)
            if ((unsigned long long)a64[i] >= (unsigned long long)INNX) is64 = 0;
        *s_is64 = is64;
    }
    __syncthreads();
    const int is64 = *s_is64;

    const int o_base = blockIdx.x * OB;
    const int o      = o_base + w;

    // neighbor indices + pooling weights, distributed in lanes 0..15
    unsigned av = 0;
    float    wv = 0.f;
    if (lane < MAXD) {
        av = is64 ? (unsigned)((const long long*)Araw)[(size_t)o * MAXD + lane]
                  : (unsigned)((const int*)Araw)[(size_t)o * MAXD + lane];
        wv = mw[o * MAXD + lane] * mask[o * MAXD + lane];
    }

    const char* fbase = (const char*)g_feat_h;

    // ---- issue helper: batch of 4 rows into ring slots (d & 7) ----
#define ISSUE_BATCH(d0)                                                        \
    {                                                                          \
        _Pragma("unroll")                                                      \
        for (int r = 0; r < 4; r++) {                                          \
            const unsigned idx = __shfl_sync(0xffffffffu, av, (d0) + r);       \
            const char* src = fbase + (size_t)idx * 1024 + lane * 16;          \
            const uint32_t dst = bufs + (((d0) + r) & 7) * 1024 + lane * 16;   \
            cpasync16(dst, src);                                               \
            cpasync16(dst + 512, src + 512);                                   \
        }                                                                      \
        asm volatile("cp.async.commit_group;" ::: "memory");                   \
    }

#define POOL_BATCH(d0)                                                         \
    {                                                                          \
        _Pragma("unroll")                                                      \
        for (int r = 0; r < 4; r++) {                                          \
            const float   wd = __shfl_sync(0xffffffffu, wv, (d0) + r);         \
            const __half2 wh = __half2half2(__float2half_rn(wd));              \
            const char* sl = bufc + (((d0) + r) & 7) * 1024 + lane * 16;       \
            uint4 u0 = *(const uint4*)sl;                                      \
            uint4 u1 = *(const uint4*)(sl + 512);                              \
            const __half2* h0 = (const __half2*)&u0;                           \
            const __half2* h1 = (const __half2*)&u1;                           \
            _Pragma("unroll")                                                  \
            for (int q = 0; q < 4; q++) {                                      \
                acc[q]     = __hfma2(h0[q], wh, acc[q]);                       \
                acc[4 + q] = __hfma2(h1[q], wh, acc[4 + q]);                   \
            }                                                                  \
        }                                                                      \
    }

    __half2 acc[8];
#pragma unroll
    for (int i = 0; i < 8; i++) acc[i] = __float2half2_rn(0.f);

    ISSUE_BATCH(0);
    ISSUE_BATCH(4);
    asm volatile("cp.async.wait_group 1;" ::: "memory");
    POOL_BATCH(0);
    ISSUE_BATCH(8);
    asm volatile("cp.async.wait_group 1;" ::: "memory");
    POOL_BATCH(4);
    ISSUE_BATCH(12);
    asm volatile("cp.async.wait_group 1;" ::: "memory");
    POOL_BATCH(8);
    asm volatile("cp.async.wait_group 0;" ::: "memory");
    POOL_BATCH(12);

    // permuted pooled stores: 4 coalesced conflict-free STS.128
    float4* sp4 = (float4*)s_pool;
    {
        float2 f0 = __half22float2(acc[0]), f1 = __half22float2(acc[1]);
        float2 f2 = __half22float2(acc[2]), f3 = __half22float2(acc[3]);
        float2 f4 = __half22float2(acc[4]), f5 = __half22float2(acc[5]);
        float2 f6 = __half22float2(acc[6]), f7 = __half22float2(acc[7]);
        sp4[lane]      = make_float4(f0.x, f0.y, f1.x, f1.y);
        sp4[32 + lane] = make_float4(f2.x, f2.y, f3.x, f3.y);
        sp4[64 + lane] = make_float4(f4.x, f4.y, f5.x, f5.y);
        sp4[96 + lane] = make_float4(f6.x, f6.y, f7.x, f7.y);
    }
    __syncwarp();

    // ---- ct_weight row packed in f32x2 regs ----
    unsigned long long wp[16];
    {
        const float4* cw4 = (const float4*)(ctw + lane * INCC);
#pragma unroll
        for (int q = 0; q < 8; q++) {
            float4 v = __ldg(cw4 + q);
            wp[2 * q]     = pk2(v.x, v.y);
            wp[2 * q + 1] = pk2(v.z, v.w);
        }
    }
    const float cb = __ldg(ctb + lane);

    // ---- GEMM in FFMA2 ----
    const ulonglong2* spv = (const ulonglong2*)s_pool;
#pragma unroll
    for (int t = 0; t < NB; t++) {
        unsigned long long y2 = pk2(cb, 0.f);
#pragma unroll
        for (int c4 = 0; c4 < 8; c4++) {
            const int idx = ((t >> 3) ? 64 : 0) + ((c4 & 1) ? 32 : 0)
                          + 4 * (t & 7) + (c4 >> 1);
            ulonglong2 pv = spv[idx];
            y2 = ffma2(pv.x, wp[2 * c4], y2);
            y2 = ffma2(pv.y, wp[2 * c4 + 1], y2);
        }
        float lo, hi; upk2(y2, lo, hi);
        s_stage[(t * 32 + lane) * (OB + 1) + w] = lo + hi;
    }
    __syncthreads();

    // ---- coalesced write-out: out[row*8192 + o] = stage + bias ----
#pragma unroll
    for (int e = tid; e < NF * OB; e += 256) {
        const int row  = e >> 3;
        const int col  = e & 7;
        const int oo   = o_base + col;
        const int dout = row & 31;
        out[(size_t)row * OUTNX + oo] =
            s_stage[row * (OB + 1) + col] + __ldg(bias + (size_t)dout * OUTNX + oo);
    }
#undef ISSUE_BATCH
#undef POOL_BATCH
}

extern "C" void kernel_launch(void* const* d_in, const int* in_sizes, int n_in,
                              void* d_out, int out_size) {
    const float* x    = (const float*)d_in[0];
    const void*  A    = d_in[1];
    const float* w    = (const float*)d_in[2];
    const float* mask = (const float*)d_in[3];
    const float* mw   = (const float*)d_in[4];
    const float* ctw  = (const float*)d_in[5];
    const float* ctb  = (const float*)d_in[6];
    const float* bias = (const float*)d_in[7];
    float* out = (float*)d_out;
    (void)in_sizes; (void)n_in; (void)out_size;

    cudaFuncSetAttribute(gather_kernel,
                         cudaFuncAttributeMaxDynamicSharedMemorySize, SM_TOTAL);

    dim3 pgrid(INNX / 64, NF / 64);
    dim3 pblk(32, 8);
    prep_kernel<<<pgrid, pblk>>>(x, w);

    gather_kernel<<<OUTNX / OB, 256, SM_TOTAL>>>(A, mask, mw, ctw, ctb, bias, out);
}

// round 10
// speedup vs baseline: 1.1556x; 1.1023x over previous
#include <cuda_runtime.h>
#include <cuda_fp16.h>
#include <cstdint>

// Problem constants (fixed by dataset)
#define NB    16
#define INCC  32
#define INNX  65536
#define OUTCC 32
#define OUTNX 8192
#define MAXD  16
#define NF    512     // NB*INCC feature columns
#define OB    8       // output nodes per CTA (one per warp)

// 64 MB fp16 feature table: feat[inn][j] = x[n,c,inn]*weight[c,inn], j = n*32+c
__device__ __half g_feat_h[(size_t)INNX * NF];

// ---- packed f32x2 helpers (sm_103a FFMA2) ----
__device__ __forceinline__ unsigned long long pk2(float lo, float hi) {
    unsigned long long r;
    asm("mov.b64 %0,{%1,%2};" : "=l"(r) : "f"(lo), "f"(hi));
    return r;
}
__device__ __forceinline__ void upk2(unsigned long long v, float& lo, float& hi) {
    asm("mov.b64 {%0,%1},%2;" : "=f"(lo), "=f"(hi) : "l"(v));
}
__device__ __forceinline__ unsigned long long ffma2(unsigned long long a,
                                                    unsigned long long b,
                                                    unsigned long long c) {
    unsigned long long d;
    asm("fma.rn.f32x2 %0,%1,%2,%3;" : "=l"(d) : "l"(a), "l"(b), "l"(c));
    return d;
}

// 16B global load bypassing L1 allocation (keeps L1 banks free for real work)
__device__ __forceinline__ uint4 ldg_nc_na128(const void* p) {
    uint4 v;
    asm volatile("ld.global.nc.L1::no_allocate.v4.u32 {%0,%1,%2,%3}, [%4];"
                 : "=r"(v.x), "=r"(v.y), "=r"(v.z), "=r"(v.w) : "l"(p));
    return v;
}

// ---------------------------------------------------------------------------
// Kernel 1 (unchanged, proven ~33us): fused scale + transpose + fp32->fp16.
// ---------------------------------------------------------------------------
__global__ __launch_bounds__(256) void prep_kernel(const float* __restrict__ x,
                                                   const float* __restrict__ w) {
    __shared__ __half2 t2[32][65];
    const unsigned inn0 = blockIdx.x << 6;
    const unsigned j0   = blockIdx.y << 6;
    const unsigned tx = threadIdx.x, ty = threadIdx.y;   // 32 x 8

#pragma unroll
    for (int k = 0; k < 4; k++) {
        const unsigned jh = ty + (k << 3);
        const unsigned j  = j0 + 2 * jh;
        const unsigned c0 = j & 31;
        const unsigned c1 = (j + 1) & 31;
        const unsigned bx0 = j * INNX + inn0 + tx;
        const unsigned bw0 = c0 * INNX + inn0 + tx;
        const unsigned bw1 = c1 * INNX + inn0 + tx;
        const float a0 = __ldcs(x + bx0)              * __ldg(w + bw0);
        const float b0 = __ldcs(x + bx0 + INNX)       * __ldg(w + bw1);
        const float a1 = __ldcs(x + bx0 + 32)         * __ldg(w + bw0 + 32);
        const float b1 = __ldcs(x + bx0 + INNX + 32)  * __ldg(w + bw1 + 32);
        t2[jh][tx]      = __floats2half2_rn(a0, b0);
        t2[jh][tx + 32] = __floats2half2_rn(a1, b1);
    }
    __syncthreads();

    __half2* out2 = (__half2*)g_feat_h;   // row stride = 256 half2
    const unsigned tid = (ty << 5) + tx;
#pragma unroll
    for (int k = 0; k < 8; k++) {
        const unsigned e     = tid + (k << 8);
        const unsigned inn_l = e >> 5;
        const unsigned jh    = e & 31;
        out2[(inn0 + inn_l) * 256u + (j0 >> 1) + jh] = t2[jh][inn_l];
    }
}

// ---------------------------------------------------------------------------
// Kernel 2 (R7 structure): FUSED warp-per-output-node gather (L1-bypass LDG)
// + HFMA2 pool + FFMA2 GEMM + staged transposed store.
// ---------------------------------------------------------------------------
__global__ __launch_bounds__(256, 4) void gather_kernel(
    const void*  __restrict__ Araw,
    const float* __restrict__ mask,
    const float* __restrict__ mw,
    const float* __restrict__ ctw,
    const float* __restrict__ ctb,
    const float* __restrict__ bias,
    float* __restrict__ out)
{
    __shared__ __align__(16) float s_pool[OB][NF];   // permuted pooled (16 KB)
    __shared__ float s_stage[NF][OB + 1];            // output staging (18 KB)
    __shared__ int   s_is64;

    const int tid  = threadIdx.x;
    const int w    = tid >> 5;
    const int lane = tid & 31;

    if (tid == 0) {
        const long long* a64 = (const long long*)Araw;
        int is64 = 1;
#pragma unroll
        for (int i = 0; i < 8; i++)
            if ((unsigned long long)a64[i] >= (unsigned long long)INNX) is64 = 0;
        s_is64 = is64;
    }
    __syncthreads();
    const int is64 = s_is64;

    const int o_base = blockIdx.x * OB;
    const int o      = o_base + w;

    // neighbor indices + pooling weights, distributed in lanes 0..15
    unsigned av = 0;
    float    wv = 0.f;
    if (lane < MAXD) {
        av = is64 ? (unsigned)((const long long*)Araw)[(size_t)o * MAXD + lane]
                  : (unsigned)((const int*)Araw)[(size_t)o * MAXD + lane];
        wv = mw[o * MAXD + lane] * mask[o * MAXD + lane];
    }

    // ---- gather + pool in half2 (HFMA2): lane covers uint4 cols {lane, lane+32} ----
    const char* fbase = (const char*)g_feat_h;
    __half2 acc[8];
#pragma unroll
    for (int i = 0; i < 8; i++) acc[i] = __float2half2_rn(0.f);

#pragma unroll
    for (int d = 0; d < MAXD; d++) {
        const unsigned idx = __shfl_sync(0xffffffffu, av, d);
        const float    wd  = __shfl_sync(0xffffffffu, wv, d);
        const __half2  wh  = __half2half2(__float2half_rn(wd));
        const char* rp = fbase + (size_t)idx * 1024 + lane * 16;
        uint4 u0 = ldg_nc_na128(rp);
        uint4 u1 = ldg_nc_na128(rp + 512);
        const __half2* h0 = (const __half2*)&u0;
        const __half2* h1 = (const __half2*)&u1;
#pragma unroll
        for (int q = 0; q < 4; q++) {
            acc[q]     = __hfma2(h0[q], wh, acc[q]);
            acc[4 + q] = __hfma2(h1[q], wh, acc[4 + q]);
        }
    }

    // permuted pooled stores: 4 coalesced conflict-free STS.128
    float4* sp4 = (float4*)s_pool[w];
    {
        float2 f0 = __half22float2(acc[0]), f1 = __half22float2(acc[1]);
        float2 f2 = __half22float2(acc[2]), f3 = __half22float2(acc[3]);
        float2 f4 = __half22float2(acc[4]), f5 = __half22float2(acc[5]);
        float2 f6 = __half22float2(acc[6]), f7 = __half22float2(acc[7]);
        sp4[lane]      = make_float4(f0.x, f0.y, f1.x, f1.y);
        sp4[32 + lane] = make_float4(f2.x, f2.y, f3.x, f3.y);
        sp4[64 + lane] = make_float4(f4.x, f4.y, f5.x, f5.y);
        sp4[96 + lane] = make_float4(f6.x, f6.y, f7.x, f7.y);
    }
    __syncwarp();

    // ---- ct_weight row packed in f32x2 regs AFTER gather ----
    unsigned long long wp[16];
    {
        const float4* cw4 = (const float4*)(ctw + lane * INCC);
#pragma unroll
        for (int q = 0; q < 8; q++) {
            float4 v = __ldg(cw4 + q);
            wp[2 * q]     = pk2(v.x, v.y);
            wp[2 * q + 1] = pk2(v.z, v.w);
        }
    }
    const float cb = __ldg(ctb + lane);

    // ---- GEMM in FFMA2 ----
    const ulonglong2* spv = (const ulonglong2*)s_pool[w];
#pragma unroll
    for (int t = 0; t < NB; t++) {
        unsigned long long y2 = pk2(cb, 0.f);
#pragma unroll
        for (int c4 = 0; c4 < 8; c4++) {
            const int idx = ((t >> 3) ? 64 : 0) + ((c4 & 1) ? 32 : 0)
                          + 4 * (t & 7) + (c4 >> 1);
            ulonglong2 pv = spv[idx];
            y2 = ffma2(pv.x, wp[2 * c4], y2);
            y2 = ffma2(pv.y, wp[2 * c4 + 1], y2);
        }
        float lo, hi; upk2(y2, lo, hi);
        s_stage[t * 32 + lane][w] = lo + hi;
    }
    __syncthreads();

    // ---- coalesced write-out: out[row*8192 + o] = stage + bias ----
#pragma unroll
    for (int e = tid; e < NF * OB; e += 256) {
        const int row  = e >> 3;
        const int col  = e & 7;
        const int oo   = o_base + col;
        const int dout = row & 31;
        out[(size_t)row * OUTNX + oo] = s_stage[row][col] + __ldg(bias + (size_t)dout * OUTNX + oo);
    }
}

extern "C" void kernel_launch(void* const* d_in, const int* in_sizes, int n_in,
                              void* d_out, int out_size) {
    const float* x    = (const float*)d_in[0];
    const void*  A    = d_in[1];
    const float* w    = (const float*)d_in[2];
    const float* mask = (const float*)d_in[3];
    const float* mw   = (const float*)d_in[4];
    const float* ctw  = (const float*)d_in[5];
    const float* ctb  = (const float*)d_in[6];
    const float* bias = (const float*)d_in[7];
    float* out = (float*)d_out;
    (void)in_sizes; (void)n_in; (void)out_size;

    // Try to pin the feature table as L2-persisting via launch attributes
    // (graph-capturable; no device limits touched). Skipped if unsupported.
    void* feat_ptr = nullptr;
    cudaGetSymbolAddress(&feat_ptr, g_feat_h);
    int dev = 0;
    cudaGetDevice(&dev);
    int maxWin = 0;
    cudaDeviceGetAttribute(&maxWin, cudaDevAttrMaxAccessPolicyWindowSize, dev);

    cudaLaunchAttribute attrs[1];
    int nattr = 0;
    if (maxWin > 0 && feat_ptr) {
        size_t winBytes = (size_t)INNX * NF * sizeof(__half);
        if (winBytes > (size_t)maxWin) winBytes = (size_t)maxWin;
        attrs[0].id = cudaLaunchAttributeAccessPolicyWindow;
        attrs[0].val.accessPolicyWindow.base_ptr  = feat_ptr;
        attrs[0].val.accessPolicyWindow.num_bytes = winBytes;
        attrs[0].val.accessPolicyWindow.hitRatio  = 1.0f;
        attrs[0].val.accessPolicyWindow.hitProp   = cudaAccessPropertyPersisting;
        attrs[0].val.accessPolicyWindow.missProp  = cudaAccessPropertyStreaming;
        nattr = 1;
    }

    {
        cudaLaunchConfig_t cfg = {};
        cfg.gridDim  = dim3(INNX / 64, NF / 64);
        cfg.blockDim = dim3(32, 8);
        cfg.stream   = 0;
        cfg.attrs    = attrs;
        cfg.numAttrs = nattr;
        cudaLaunchKernelEx(&cfg, prep_kernel, x, w);
    }
    {
        cudaLaunchConfig_t cfg = {};
        cfg.gridDim  = dim3(OUTNX / OB);
        cfg.blockDim = dim3(256);
        cfg.stream   = 0;
        cfg.attrs    = attrs;
        cfg.numAttrs = nattr;
        cudaLaunchKernelEx(&cfg, gather_kernel, (const void*)A, mask, mw, ctw, ctb, bias, out);
    }
}